// round 1
// baseline (speedup 1.0000x reference)
#include <cuda_runtime.h>
#include <cuda_fp16.h>

#define H        64
#define NPIX     65536
#define LBATCH   8
#define NLC      24
#define NSPLIT   64                      // K-splits (warps) per (l,c)
#define PIX_PER_WARP (NPIX / NSPLIT)     // 1024
#define NCHUNK   (PIX_PER_WARP / 32)     // 32 chunks of 32 pixels

// scratch: per-warp partial 64x64 tiles, [NLC][NSPLIT][H*H]
__device__ float g_part[NLC * NSPLIT * H * H];
__device__ float g_totals[LBATCH];

__device__ __forceinline__ float rq(float d) {
    // 1 / (1 + d*d)
    float t = fmaf(d, d, 1.0f);
    float r; asm("rcp.approx.ftz.f32 %0, %1;" : "=f"(r) : "f"(t));
    return r;
}
__device__ __forceinline__ unsigned pk(float lo, float hi) {
    // pack two f32 -> f16x2, lo in lower half
    unsigned r; asm("cvt.rn.f16x2.f32 %0, %2, %1;" : "=r"(r) : "f"(lo), "f"(hi));
    return r;
}
__device__ __forceinline__ float lg2a(float x) {
    float r; asm("lg2.approx.f32 %0, %1;" : "=f"(r) : "f"(x));
    return r;
}
__device__ __forceinline__ float sqrta(float x) {
    float r; asm("sqrt.approx.f32 %0, %1;" : "=f"(r) : "f"(x));
    return r;
}
__device__ __forceinline__ void mma16816(float* c, const unsigned* a, unsigned b0, unsigned b1) {
    asm volatile(
        "mma.sync.aligned.m16n8k16.row.col.f32.f16.f16.f32 "
        "{%0,%1,%2,%3}, {%4,%5,%6,%7}, {%8,%9}, {%0,%1,%2,%3};"
        : "+f"(c[0]), "+f"(c[1]), "+f"(c[2]), "+f"(c[3])
        : "r"(a[0]), "r"(a[1]), "r"(a[2]), "r"(a[3]), "r"(b0), "r"(b1));
}

// grid: (NSPLIT, NLC), block: 32 threads (one warp)
__global__ __launch_bounds__(32) void hist_main(const float* __restrict__ x) {
    const int lane = threadIdx.x;
    const int lc = blockIdx.y;
    const int l = lc / 3, c = lc % 3;
    const float* __restrict__ xl = x + (size_t)l * 3 * NPIX;
    const int pixbase = blockIdx.x * PIX_PER_WARP;

    float acc[4][8][4];
#pragma unroll
    for (int m = 0; m < 4; m++)
#pragma unroll
        for (int j = 0; j < 8; j++)
#pragma unroll
            for (int k = 0; k < 4; k++) acc[m][j][k] = 0.0f;

    // bin centers in scaled coords: off(i) = (-3 + i*6/63) / sigma, sigma = 0.02
    float rowoff[8];
#pragma unroll
    for (int i = 0; i < 8; i++)
        rowoff[i] = (-3.0f + (float)((lane >> 2) + 8 * i) * (6.0f / 63.0f)) * 50.0f;

    const float SC = 34.65735903f;  // ln(2) / sigma  (lg2 -> ln, then /sigma)
    const int kc = (lane & 3) * 2;

#pragma unroll 1
    for (int ch = 0; ch < NCHUNK; ch++) {
        const int p = pixbase + ch * 32 + lane;
        float i0 = fminf(fmaxf(xl[p], 0.0f), 1.0f);
        float i1 = fminf(fmaxf(xl[p + NPIX], 0.0f), 1.0f);
        float i2 = fminf(fmaxf(xl[p + 2 * NPIX], 0.0f), 1.0f);
        float w = sqrta(fmaf(i0, i0, fmaf(i1, i1, fmaf(i2, i2, 1e-6f))));
        float g0 = lg2a(i0 + 1e-6f);
        float g1 = lg2a(i1 + 1e-6f);
        float g2 = lg2a(i2 + 1e-6f);
        // per-channel log-chromaticity, scaled by 1/sigma
        float au, av;
        if (c == 0)      { au = (g0 - g1) * SC; av = (g0 - g2) * SC; }
        else if (c == 1) { au = (g1 - g0) * SC; av = (g1 - g2) * SC; }
        else             { au = (g2 - g0) * SC; av = (g2 - g1) * SC; }

#pragma unroll
        for (int s = 0; s < 2; s++) {
            const int sb = s * 16 + kc;
            float au0 = __shfl_sync(0xffffffffu, au, sb);
            float au1 = __shfl_sync(0xffffffffu, au, sb + 1);
            float au2 = __shfl_sync(0xffffffffu, au, sb + 8);
            float au3 = __shfl_sync(0xffffffffu, au, sb + 9);
            float av0 = __shfl_sync(0xffffffffu, av, sb);
            float av1 = __shfl_sync(0xffffffffu, av, sb + 1);
            float av2 = __shfl_sync(0xffffffffu, av, sb + 8);
            float av3 = __shfl_sync(0xffffffffu, av, sb + 9);
            float w0 = __shfl_sync(0xffffffffu, w, sb);
            float w1 = __shfl_sync(0xffffffffu, w, sb + 1);
            float w2 = __shfl_sync(0xffffffffu, w, sb + 8);
            float w3 = __shfl_sync(0xffffffffu, w, sb + 9);

            // A fragments: A[u][k] = w_k * Ku  (4 M-tiles of 16 rows)
            unsigned a[4][4];
#pragma unroll
            for (int m = 0; m < 4; m++) {
                const float o0 = rowoff[2 * m];      // row r = lane/4 + 16m
                const float o1 = rowoff[2 * m + 1];  // row r + 8
                a[m][0] = pk(w0 * rq(au0 - o0), w1 * rq(au1 - o0));
                a[m][1] = pk(w0 * rq(au0 - o1), w1 * rq(au1 - o1));
                a[m][2] = pk(w2 * rq(au2 - o0), w3 * rq(au3 - o0));
                a[m][3] = pk(w2 * rq(au2 - o1), w3 * rq(au3 - o1));
            }
            // B fragments per N-tile j: B[k][v] = Kv, col v = lane/4 + 8j
#pragma unroll
            for (int j = 0; j < 8; j++) {
                const float o = rowoff[j];
                unsigned b0 = pk(rq(av0 - o), rq(av1 - o));
                unsigned b1 = pk(rq(av2 - o), rq(av3 - o));
#pragma unroll
                for (int m = 0; m < 4; m++) mma16816(acc[m][j], a[m], b0, b1);
            }
        }
    }

    // store partial tile (non-atomic, private slot)
    float* dst = g_part + ((size_t)lc * NSPLIT + blockIdx.x) * (H * H);
    const int r = lane >> 2;
    const int q = (lane & 3) * 2;
#pragma unroll
    for (int m = 0; m < 4; m++)
#pragma unroll
        for (int j = 0; j < 8; j++) {
            const int row0 = m * 16 + r;
            const int col = j * 8 + q;
            *(float2*)(dst + row0 * H + col)       = make_float2(acc[m][j][0], acc[m][j][1]);
            *(float2*)(dst + (row0 + 8) * H + col) = make_float2(acc[m][j][2], acc[m][j][3]);
        }
}

__global__ void zero_totals() {
    if (threadIdx.x < LBATCH) g_totals[threadIdx.x] = 0.0f;
}

// grid: (16, NLC), block 256 — sum 64 partials per element; accumulate per-l totals
__global__ void hist_reduce(float* __restrict__ out) {
    const int lc = blockIdx.y;
    const int e = blockIdx.x * 256 + threadIdx.x;  // 0..4095
    const float* __restrict__ src = g_part + (size_t)lc * NSPLIT * (H * H) + e;
    float s = 0.0f;
#pragma unroll 8
    for (int p = 0; p < NSPLIT; p++) s += src[(size_t)p * (H * H)];
    out[lc * (H * H) + e] = s;

    __shared__ float red[256];
    red[threadIdx.x] = s;
    __syncthreads();
#pragma unroll
    for (int st = 128; st > 0; st >>= 1) {
        if (threadIdx.x < st) red[threadIdx.x] += red[threadIdx.x + st];
        __syncthreads();
    }
    if (threadIdx.x == 0) atomicAdd(&g_totals[lc / 3], red[0]);
}

__global__ void hist_norm(float* __restrict__ out) {
    const int idx = blockIdx.x * 256 + threadIdx.x;
    if (idx < NLC * H * H) {
        const int l = idx / (3 * H * H);
        out[idx] = out[idx] / (g_totals[l] + 1e-6f);
    }
}

extern "C" void kernel_launch(void* const* d_in, const int* in_sizes, int n_in,
                              void* d_out, int out_size) {
    const float* x = (const float*)d_in[0];
    float* out = (float*)d_out;
    (void)in_sizes; (void)n_in; (void)out_size;

    zero_totals<<<1, 32>>>();
    hist_main<<<dim3(NSPLIT, NLC), 32>>>(x);
    hist_reduce<<<dim3(16, NLC), 256>>>(out);
    hist_norm<<<(NLC * H * H + 255) / 256, 256>>>(out);
}

// round 2
// speedup vs baseline: 1.0120x; 1.0120x over previous
#include <cuda_runtime.h>
#include <cuda_fp16.h>

#define H        64
#define NPIX     65536
#define LBATCH   8
#define NLC      24
#define NSPLIT   64                      // K-splits (warps) per (l,c)
#define PIX_PER_WARP (NPIX / NSPLIT)     // 1024
#define NCHUNK   (PIX_PER_WARP / 32)     // 32 chunks of 32 pixels

// scratch: per-warp partial 64x64 tiles, [NLC][NSPLIT][H*H]
__device__ float g_part[NLC * NSPLIT * H * H];
__device__ float g_totals[LBATCH];

__device__ __forceinline__ float rq(float d) {
    // 1 / (1 + d*d)
    float t = fmaf(d, d, 1.0f);
    float r; asm("rcp.approx.ftz.f32 %0, %1;" : "=f"(r) : "f"(t));
    return r;
}
__device__ __forceinline__ unsigned pk(float lo, float hi) {
    // pack two f32 -> f16x2, lo in lower half
    unsigned r; asm("cvt.rn.f16x2.f32 %0, %2, %1;" : "=r"(r) : "f"(lo), "f"(hi));
    return r;
}
__device__ __forceinline__ float lg2a(float x) {
    float r; asm("lg2.approx.f32 %0, %1;" : "=f"(r) : "f"(x));
    return r;
}
__device__ __forceinline__ float sqrta(float x) {
    float r; asm("sqrt.approx.f32 %0, %1;" : "=f"(r) : "f"(x));
    return r;
}
__device__ __forceinline__ void mma16816(float* c, const unsigned* a, unsigned b0, unsigned b1) {
    asm volatile(
        "mma.sync.aligned.m16n8k16.row.col.f32.f16.f16.f32 "
        "{%0,%1,%2,%3}, {%4,%5,%6,%7}, {%8,%9}, {%0,%1,%2,%3};"
        : "+f"(c[0]), "+f"(c[1]), "+f"(c[2]), "+f"(c[3])
        : "r"(a[0]), "r"(a[1]), "r"(a[2]), "r"(a[3]), "r"(b0), "r"(b1));
}

// grid: (NSPLIT, NLC), block: 32 threads (one warp)
__global__ __launch_bounds__(32) void hist_main(const float* __restrict__ x) {
    const int lane = threadIdx.x;
    const int lc = blockIdx.y;
    const int l = lc / 3, c = lc % 3;
    const float* __restrict__ xl = x + (size_t)l * 3 * NPIX;
    const int pixbase = blockIdx.x * PIX_PER_WARP;

    float acc[4][8][4];
#pragma unroll
    for (int m = 0; m < 4; m++)
#pragma unroll
        for (int j = 0; j < 8; j++)
#pragma unroll
            for (int k = 0; k < 4; k++) acc[m][j][k] = 0.0f;

    // bin centers in scaled coords: off(i) = (-3 + i*6/63) / sigma, sigma = 0.02
    float rowoff[8];
#pragma unroll
    for (int i = 0; i < 8; i++)
        rowoff[i] = (-3.0f + (float)((lane >> 2) + 8 * i) * (6.0f / 63.0f)) * 50.0f;

    const float SC = 34.65735903f;  // ln(2) / sigma  (lg2 -> ln, then /sigma)
    const int kc = (lane & 3) * 2;

#pragma unroll 1
    for (int ch = 0; ch < NCHUNK; ch++) {
        const int p = pixbase + ch * 32 + lane;
        float i0 = fminf(fmaxf(xl[p], 0.0f), 1.0f);
        float i1 = fminf(fmaxf(xl[p + NPIX], 0.0f), 1.0f);
        float i2 = fminf(fmaxf(xl[p + 2 * NPIX], 0.0f), 1.0f);
        float w = sqrta(fmaf(i0, i0, fmaf(i1, i1, fmaf(i2, i2, 1e-6f))));
        float g0 = lg2a(i0 + 1e-6f);
        float g1 = lg2a(i1 + 1e-6f);
        float g2 = lg2a(i2 + 1e-6f);
        // per-channel log-chromaticity, scaled by 1/sigma
        float au, av;
        if (c == 0)      { au = (g0 - g1) * SC; av = (g0 - g2) * SC; }
        else if (c == 1) { au = (g1 - g0) * SC; av = (g1 - g2) * SC; }
        else             { au = (g2 - g0) * SC; av = (g2 - g1) * SC; }

#pragma unroll
        for (int s = 0; s < 2; s++) {
            const int sb = s * 16 + kc;
            float au0 = __shfl_sync(0xffffffffu, au, sb);
            float au1 = __shfl_sync(0xffffffffu, au, sb + 1);
            float au2 = __shfl_sync(0xffffffffu, au, sb + 8);
            float au3 = __shfl_sync(0xffffffffu, au, sb + 9);
            float av0 = __shfl_sync(0xffffffffu, av, sb);
            float av1 = __shfl_sync(0xffffffffu, av, sb + 1);
            float av2 = __shfl_sync(0xffffffffu, av, sb + 8);
            float av3 = __shfl_sync(0xffffffffu, av, sb + 9);
            float w0 = __shfl_sync(0xffffffffu, w, sb);
            float w1 = __shfl_sync(0xffffffffu, w, sb + 1);
            float w2 = __shfl_sync(0xffffffffu, w, sb + 8);
            float w3 = __shfl_sync(0xffffffffu, w, sb + 9);

            // A fragments: A[u][k] = w_k * Ku  (4 M-tiles of 16 rows)
            unsigned a[4][4];
#pragma unroll
            for (int m = 0; m < 4; m++) {
                const float o0 = rowoff[2 * m];      // row r = lane/4 + 16m
                const float o1 = rowoff[2 * m + 1];  // row r + 8
                a[m][0] = pk(w0 * rq(au0 - o0), w1 * rq(au1 - o0));
                a[m][1] = pk(w0 * rq(au0 - o1), w1 * rq(au1 - o1));
                a[m][2] = pk(w2 * rq(au2 - o0), w3 * rq(au3 - o0));
                a[m][3] = pk(w2 * rq(au2 - o1), w3 * rq(au3 - o1));
            }
            // B fragments per N-tile j: B[k][v] = Kv, col v = lane/4 + 8j
#pragma unroll
            for (int j = 0; j < 8; j++) {
                const float o = rowoff[j];
                unsigned b0 = pk(rq(av0 - o), rq(av1 - o));
                unsigned b1 = pk(rq(av2 - o), rq(av3 - o));
#pragma unroll
                for (int m = 0; m < 4; m++) mma16816(acc[m][j], a[m], b0, b1);
            }
        }
    }

    // store partial tile (non-atomic, private slot)
    float* dst = g_part + ((size_t)lc * NSPLIT + blockIdx.x) * (H * H);
    const int r = lane >> 2;
    const int q = (lane & 3) * 2;
#pragma unroll
    for (int m = 0; m < 4; m++)
#pragma unroll
        for (int j = 0; j < 8; j++) {
            const int row0 = m * 16 + r;
            const int col = j * 8 + q;
            *(float2*)(dst + row0 * H + col)       = make_float2(acc[m][j][0], acc[m][j][1]);
            *(float2*)(dst + (row0 + 8) * H + col) = make_float2(acc[m][j][2], acc[m][j][3]);
        }
}

__global__ void zero_totals() {
    if (threadIdx.x < LBATCH) g_totals[threadIdx.x] = 0.0f;
}

// grid: (16, NLC), block 256 — sum 64 partials per element; accumulate per-l totals
__global__ void hist_reduce(float* __restrict__ out) {
    const int lc = blockIdx.y;
    const int e = blockIdx.x * 256 + threadIdx.x;  // 0..4095
    const float* __restrict__ src = g_part + (size_t)lc * NSPLIT * (H * H) + e;
    float s = 0.0f;
#pragma unroll 8
    for (int p = 0; p < NSPLIT; p++) s += src[(size_t)p * (H * H)];
    out[lc * (H * H) + e] = s;

    __shared__ float red[256];
    red[threadIdx.x] = s;
    __syncthreads();
#pragma unroll
    for (int st = 128; st > 0; st >>= 1) {
        if (threadIdx.x < st) red[threadIdx.x] += red[threadIdx.x + st];
        __syncthreads();
    }
    if (threadIdx.x == 0) atomicAdd(&g_totals[lc / 3], red[0]);
}

__global__ void hist_norm(float* __restrict__ out) {
    const int idx = blockIdx.x * 256 + threadIdx.x;
    if (idx < NLC * H * H) {
        const int l = idx / (3 * H * H);
        out[idx] = out[idx] / (g_totals[l] + 1e-6f);
    }
}

extern "C" void kernel_launch(void* const* d_in, const int* in_sizes, int n_in,
                              void* d_out, int out_size) {
    const float* x = (const float*)d_in[0];
    float* out = (float*)d_out;
    (void)in_sizes; (void)n_in; (void)out_size;

    zero_totals<<<1, 32>>>();
    hist_main<<<dim3(NSPLIT, NLC), 32>>>(x);
    hist_reduce<<<dim3(16, NLC), 256>>>(out);
    hist_norm<<<(NLC * H * H + 255) / 256, 256>>>(out);
}